// round 14
// baseline (speedup 1.0000x reference)
#include <cuda_runtime.h>

#define CAM_FL  540.0f
#define HALF_W  320.0f
#define HALF_H  240.0f
#define CAM_W   640
#define CAM_H   480
#define HW      (CAM_H * CAM_W)
#define TPB     128      // threads per block
#define CAP     128      // smem survivor capacity (mean ~31/block; overflow -> deferred slow path)

__device__ int g_bar1;   // blocks that finished zeroing their out-slice
__device__ int g_bar2;   // blocks that finished entirely (for counter reset)

__global__ __launch_bounds__(TPB, 8) void proj_kernel(
    const float* __restrict__ locs,
    const float* __restrict__ pose,
    const float* __restrict__ rotq,
    const float* __restrict__ depth,
    float* __restrict__ out,
    int N)
{
    // s_cam rows: rows 0,1 pre-scaled by CAM_FL. p_cam[j] = X*a0+Y*a1+Z*a2+a3
    __shared__ float s_cam[12];
    // record (16 floats): [0..7]=wx8 (aligned 8-slot x weights, pre-masked)
    // [8]=z  [9]=packed(bx | (ib+4)<<10)  [10..14]=wy[0..4]  [15]=pad
    __shared__ float s_rec[CAP][16];
    __shared__ int   s_cnt;

    const int tid   = threadIdx.x;
    const int b     = blockIdx.y;
    const int nblk  = gridDim.x * gridDim.y;
    const int blkid = blockIdx.y * gridDim.x + blockIdx.x;

    // ---------------- Stage 0: zero this block's slice of out ----------------
    {
        float4* o4 = (float4*)out;
        const int OUT4 = (gridDim.y * HW) >> 2;
        const int zc = (OUT4 + nblk - 1) / nblk;
        const int z0 = blkid * zc;
        const int z1 = min(z0 + zc, OUT4);
        for (int i = z0 + tid; i < z1; i += TPB)
            o4[i] = make_float4(0.f, 0.f, 0.f, 0.f);
    }
    __threadfence();
    __syncthreads();
    if (tid == 0) { s_cnt = 0; atomicAdd(&g_bar1, 1); }

    // ---- warp 0: quaternion -> camera matrix (translation folded, rows 0/1 x540) ----
    if (tid < 32) {
        float qx = __ldg(rotq + b * 4 + 0);
        float qy = __ldg(rotq + b * 4 + 1);
        float qz = __ldg(rotq + b * 4 + 2);
        float qw = __ldg(rotq + b * 4 + 3);
        float inv = rsqrtf(qx * qx + qy * qy + qz * qz + qw * qw);
        qx = -qx * inv; qy = -qy * inv; qz = -qz * inv; qw = qw * inv;

        const float qx2 = qx * qx, qy2 = qy * qy, qz2 = qz * qz;
        const float qxqy = qx * qy, qxqz = qx * qz, qxqw = qx * qw;
        const float qyqz = qy * qz, qyqw = qy * qw, qzqw = qz * qw;
        const float r00 = 1.f - 2.f * qy2 - 2.f * qz2;
        const float r10 = 2.f * qxqy - 2.f * qzqw;
        const float r20 = 2.f * qxqz + 2.f * qyqw;
        const float r01 = 2.f * qxqy + 2.f * qzqw;
        const float r11 = 1.f - 2.f * qx2 - 2.f * qz2;
        const float r21 = 2.f * qyqz - 2.f * qxqw;
        const float r02 = 2.f * qxqz - 2.f * qyqw;
        const float r12 = 2.f * qyqz + 2.f * qxqw;
        const float r22 = 1.f - 2.f * qx2 - 2.f * qy2;

        const float cx = __ldg(pose + b * 3 + 0);
        const float cy = __ldg(pose + b * 3 + 1);
        const float cz = __ldg(pose + b * 3 + 2);
        const float t0 = cx * r00 + cy * r10 + cz * r20;
        const float t1 = cx * r01 + cy * r11 + cz * r21;
        const float t2 = cx * r02 + cy * r12 + cz * r22;

        if (tid == 0) {
            s_cam[0] = CAM_FL*r00; s_cam[1]  = CAM_FL*r10; s_cam[2]  = CAM_FL*r20; s_cam[3]  = CAM_FL*(-t0);
            s_cam[4] = CAM_FL*r01; s_cam[5]  = CAM_FL*r11; s_cam[6]  = CAM_FL*r21; s_cam[7]  = CAM_FL*(-t1);
            s_cam[8] = r02;        s_cam[9]  = r12;        s_cam[10] = r22;        s_cam[11] = -t2;
        }
    }
    __syncthreads();   // publishes s_cam and s_cnt

    const float a00 = s_cam[0], a01 = s_cam[1],  a02 = s_cam[2],  a03 = s_cam[3];
    const float a10 = s_cam[4], a11 = s_cam[5],  a12 = s_cam[6],  a13 = s_cam[7];
    const float a20 = s_cam[8], a21 = s_cam[9],  a22 = s_cam[10], a23 = s_cam[11];

    const float* dimg = depth + b * HW;
    float*       oimg = out   + b * HW;

    const float C1 = 0.60653066f;   // exp(-0.5)
    const float C2 = 0.13533528f;   // exp(-2)

    // ---------------- Phase 1: multiply-form cull, 4/thread, chunked ----------------
    const int chunk = (((N + gridDim.x - 1) / gridDim.x) + 3) & ~3;   // 4-aligned
    const int base  = blockIdx.x * chunk;
    const float* lpb = locs + (long long)b * N * 3;

    for (int off = 0; off < chunk; off += TPB * 4) {
        const int il = off + 4 * tid;        // local particle index (4-aligned)
        const int gi = base + il;            // global particle index

        float X[4], Y[4], Z[4];
        bool hv[4];
        if (il + 4 <= chunk && gi + 4 <= N) {   // per-thread fast path: 3x LDG.128
            const float4* p = (const float4*)(lpb + (long long)gi * 3);
            const float4 A  = p[0];
            const float4 Bv = p[1];
            const float4 Cv = p[2];
            X[0] = A.x;  Y[0] = A.y;  Z[0] = A.z;
            X[1] = A.w;  Y[1] = Bv.x; Z[1] = Bv.y;
            X[2] = Bv.z; Y[2] = Bv.w; Z[2] = Cv.x;
            X[3] = Cv.y; Y[3] = Cv.z; Z[3] = Cv.w;
            hv[0] = hv[1] = hv[2] = hv[3] = true;
        } else {
#pragma unroll
            for (int j = 0; j < 4; j++) {
                hv[j] = (il + j < chunk) && (gi + j < N);
                X[j] = Y[j] = Z[j] = 0.f;
                if (hv[j]) {
                    X[j] = lpb[(long long)(gi + j) * 3];
                    Y[j] = lpb[(long long)(gi + j) * 3 + 1];
                    Z[j] = lpb[(long long)(gi + j) * 3 + 2];
                }
            }
        }

        float xs[4], ys[4], zv[4];
        bool  okv[4];
#pragma unroll
        for (int j = 0; j < 4; j++) {
            const float x = fmaf(X[j], a00, fmaf(Y[j], a01, fmaf(Z[j], a02, a03)));  // 540*x_cam
            const float y = fmaf(X[j], a10, fmaf(Y[j], a11, fmaf(Z[j], a12, a13)));  // 540*y_cam
            const float z = fmaf(X[j], a20, fmaf(Y[j], a21, fmaf(Z[j], a22, a23)));
            xs[j] = x; ys[j] = y; zv[j] = z;
            okv[j] = hv[j] && (z > 0.f) &&
                     (fabsf(x) <= 322.f * z) && (fabsf(y) <= 242.f * z);
        }

        unsigned mm[4];
#pragma unroll
        for (int j = 0; j < 4; j++) mm[j] = __ballot_sync(0xffffffffu, okv[j]);

        const int tot = __popc(mm[0]) + __popc(mm[1]) + __popc(mm[2]) + __popc(mm[3]);
        int idx[4] = {0, 0, 0, 0};
        if (tot) {
            const int lane = tid & 31;
            const unsigned lt = (1u << lane) - 1u;
            int bs = 0;
            if (lane == 0) bs = atomicAdd(&s_cnt, tot);
            bs = __shfl_sync(0xffffffffu, bs, 0);
            int run = bs;
#pragma unroll
            for (int j = 0; j < 4; j++) {
                idx[j] = run + __popc(mm[j] & lt);
                run += __popc(mm[j]);
            }
        }

#pragma unroll
        for (int j = 0; j < 4; j++) {
            if (!okv[j]) continue;
            const float z    = zv[j];
            const float invz = __frcp_rn(z);
            const float px   = xs[j] * invz + HALF_W;
            const float py   = ys[j] * invz + HALF_H;
            const int   id   = idx[j];

            // exact re-verify (cull can disagree by ~1 ulp at the window edge)
            const bool exact = (fabsf(px - HALF_W) <= 322.f) && (fabsf(py - HALF_H) <= 242.f);

            if (id < CAP) {
                float* r = s_rec[id];
                *(float4*)(r)      = make_float4(0.f, 0.f, 0.f, 0.f);
                *(float4*)(r + 4)  = make_float4(0.f, 0.f, 0.f, 0.f);
                *(float4*)(r + 8)  = make_float4(0.f, 0.f, 0.f, 0.f);
                *(float4*)(r + 12) = make_float4(0.f, 0.f, 0.f, 0.f);
                if (exact) {
                    const float fx = floorf(px), fy = floorf(py);
                    const int jb = (int)fx - 2;
                    const int ib = (int)fy - 2;                 // in [-4, 480]
                    const int bx = min(max(jb, 0) & ~3, 632);   // aligned 8-slot window
                    const int off8 = jb - bx;                   // in [-2, 8]
                    const float u = fx - px;
                    const float v = fy - py;

                    const float ax  = __expf(-0.5f * u * u);
                    const float ex  = __expf(-u);
                    const float exi = __frcp_rn(ex);
                    int s;
                    s = off8 + 0; if (s >= 0 && s <= 7) r[s] = ax * exi * exi * C2;
                    s = off8 + 1; if (s >= 0 && s <= 7) r[s] = ax * exi * C1;
                    s = off8 + 2; if (s >= 0 && s <= 7) r[s] = ax;
                    s = off8 + 3; if (s >= 0 && s <= 7) r[s] = ax * ex * C1;
                    s = off8 + 4; if (s >= 0 && s <= 7) r[s] = ax * ex * ex * C2;

                    const float ay  = __expf(-0.5f * v * v);
                    const float ey  = __expf(-v);
                    const float eyi = __frcp_rn(ey);
                    r[8]  = z;
                    r[9]  = __int_as_float(bx | ((ib + 4) << 10));
                    r[10] = ay * eyi * eyi * C2;
                    r[11] = ay * eyi * C1;
                    r[12] = ay;
                    r[13] = ay * ey * C1;
                    r[14] = ay * ey * ey * C2;
                }
                // !exact: zero record -> phase 2 no-ops on it
            } else if (exact) {
                // overflow slow path (statistically unreachable): wait for global
                // zeroing to complete, then splat directly. Deadlock-free: every
                // block arrives at g_bar1 unconditionally at kernel entry.
                while (atomicAdd(&g_bar1, 0) < nblk) __nanosleep(64);
                const float fx = floorf(px), fy = floorf(py);
                const int jb = (int)fx - 2, ib = (int)fy - 2;
                const float u = fx - px, v = fy - py;
                const float ax = __expf(-0.5f * u * u);
                const float ex = __expf(-u);
                const float exi = __frcp_rn(ex);
                const float wxv[5] = {ax*exi*exi*C2, ax*exi*C1, ax, ax*ex*C1, ax*ex*ex*C2};
                const float ay = __expf(-0.5f * v * v);
                const float ey = __expf(-v);
                const float eyi = __frcp_rn(ey);
                const float wyv[5] = {ay*eyi*eyi*C2, ay*eyi*C1, ay, ay*ey*C1, ay*ey*ey*C2};
                for (int ii = 0; ii < 5; ii++) {
                    const int yy = ib + ii;
                    if (yy < 0 || yy >= CAM_H) continue;
                    for (int jj = 0; jj < 5; jj++) {
                        const int xx = jb + jj;
                        if (xx < 0 || xx >= CAM_W) continue;
                        const float d = __ldg(dimg + yy * CAM_W + xx);
                        if (z <= d) atomicAdd(oimg + yy * CAM_W + xx, wyv[ii] * wxv[jj]);
                    }
                }
            }
        }
    }

    __syncthreads();

    // ---------------- global barrier: all out-slices zeroed ----------------
    if (tid == 0) {
        while (atomicAdd(&g_bar1, 0) < nblk) __nanosleep(128);
    }
    __syncthreads();
    __threadfence();

    // ---------------- Phase 2: warp-coalesced splat ----------------
    // 8 consecutive lanes own the 8 aligned slots of one survivor; a warp
    // processes 4 survivors. Depth loads and reds hit 4 contiguous 32B
    // segments per warp-op (coalesced), 5 rows loaded up-front (MLP=5).
    const int cnt  = min(s_cnt, CAP);
    const int wid  = tid >> 5;
    const int lane = tid & 31;
    const int sub  = lane >> 3;     // 0..3: survivor within warp-task
    const int slot = lane & 7;      // 0..7: x-slot

    for (int s0 = wid * 4; s0 < cnt; s0 += (TPB / 32) * 4) {
        const int s = s0 + sub;
        if (s >= cnt) continue;

        const float* r = s_rec[s];
        const float wx = r[slot];
        const float z  = r[8];
        const int   pk = __float_as_int(r[9]);
        const int   bx = pk & 0x3ff;
        const int   ib = ((pk >> 10) & 0x1ff) - 4;

        const int pbase = ib * CAM_W + bx + slot;

        float dd[5];
        int   oo[5];
        bool  rk[5];
#pragma unroll
        for (int row = 0; row < 5; row++) {
            const int yy = ib + row;
            rk[row] = (yy >= 0) && (yy < CAM_H) && (wx != 0.f);
            oo[row] = pbase + row * CAM_W;
            dd[row] = rk[row] ? __ldg(dimg + oo[row]) : -1.f;
        }
#pragma unroll
        for (int row = 0; row < 5; row++) {
            if (rk[row] && z <= dd[row]) {
                atomicAdd(oimg + oo[row], r[10 + row] * wx);
            }
        }
    }

    // ---------------- epilogue: reset counters for the next graph replay ----------------
    __syncthreads();
    if (tid == 0) {
        const int v = atomicAdd(&g_bar2, 1);
        if (v == nblk - 1) {        // last block out: everyone has passed g_bar1
            g_bar1 = 0;
            g_bar2 = 0;
            __threadfence();
        }
    }
}

extern "C" void kernel_launch(void* const* d_in, const int* in_sizes, int n_in,
                              void* d_out, int out_size) {
    const float* locs  = (const float*)d_in[0];
    const float* pose  = (const float*)d_in[1];
    const float* rotq  = (const float*)d_in[2];
    const float* depth = (const float*)d_in[3];
    float* out = (float*)d_out;

    const int B = in_sizes[1] / 3;           // 4
    const int N = in_sizes[0] / (3 * B);     // 200000

    // Persistent co-resident grid: total blocks <= 8/SM * 148 SMs = 1184.
    const int gx = 1184 / B;                 // 296 for B=4
    dim3 grid(gx, B);
    proj_kernel<<<grid, TPB>>>(locs, pose, rotq, depth, out, N);
}

// round 15
// speedup vs baseline: 1.2959x; 1.2959x over previous
#include <cuda_runtime.h>

#define CAM_FL  540.0f
#define HALF_W  320.0f
#define HALF_H  240.0f
#define CAM_W   640
#define CAM_H   480
#define HW      (CAM_H * CAM_W)
#define PB      512      // particles per block (2 per thread)
#define TPB     256      // threads per block
#define CAP     128      // smem survivor capacity (mean ~23/block; overflow -> slow path)

__global__ __launch_bounds__(TPB, 6) void proj_kernel(
    const float* __restrict__ locs,
    const float* __restrict__ pose,
    const float* __restrict__ rotq,
    const float* __restrict__ depth,
    float* __restrict__ out,
    int N)
{
    // s_cam rows: rows 0,1 pre-scaled by CAM_FL; p_cam[j] = X*a0 + Y*a1 + Z*a2 + a3
    __shared__ float s_cam[12];
    // record (16 floats): [0..7]=wx8 (aligned 8-slot x weights, pre-masked)
    // [8]=z  [9]=packed(bx | (ib+4)<<10)  [10..14]=wy[0..4]  [15]=pad
    __shared__ float s_rec[CAP][16];
    __shared__ int   s_cnt;

    const int tid = threadIdx.x;
    const int b   = blockIdx.y;

    if (tid == 0) s_cnt = 0;

    const int  gpart = blockIdx.x * PB;
    const float* lpB = locs + ((long long)b * N + gpart) * 3;
    const int  i0 = 2 * tid;

    // ---- issue particle loads FIRST (overlap with warp-0 camera compute) ----
    float X[2], Y[2], Z[2];
    bool hv[2];
    if (gpart + PB <= N) {           // full block (uniform fast path)
        const float2 A  = *(const float2*)(lpB + i0 * 3);
        const float2 Bv = *(const float2*)(lpB + i0 * 3 + 2);
        const float2 Cv = *(const float2*)(lpB + i0 * 3 + 4);
        X[0] = A.x;  Y[0] = A.y;  Z[0] = Bv.x;
        X[1] = Bv.y; Y[1] = Cv.x; Z[1] = Cv.y;
        hv[0] = hv[1] = true;
    } else {
        hv[0] = (gpart + i0) < N;
        hv[1] = (gpart + i0 + 1) < N;
        X[0] = Y[0] = Z[0] = X[1] = Y[1] = Z[1] = 0.f;
        if (hv[0]) { X[0] = lpB[i0*3];   Y[0] = lpB[i0*3+1]; Z[0] = lpB[i0*3+2]; }
        if (hv[1]) { X[1] = lpB[i0*3+3]; Y[1] = lpB[i0*3+4]; Z[1] = lpB[i0*3+5]; }
    }

    // ---- warp 0: quaternion -> camera matrix (translation folded, rows 0/1 x CAM_FL) ----
    if (tid < 32) {
        float qx = __ldg(rotq + b * 4 + 0);
        float qy = __ldg(rotq + b * 4 + 1);
        float qz = __ldg(rotq + b * 4 + 2);
        float qw = __ldg(rotq + b * 4 + 3);
        float inv = rsqrtf(qx * qx + qy * qy + qz * qz + qw * qw);
        qx = -qx * inv; qy = -qy * inv; qz = -qz * inv; qw = qw * inv;

        const float qx2 = qx * qx, qy2 = qy * qy, qz2 = qz * qz;
        const float qxqy = qx * qy, qxqz = qx * qz, qxqw = qx * qw;
        const float qyqz = qy * qz, qyqw = qy * qw, qzqw = qz * qw;
        const float r00 = 1.f - 2.f * qy2 - 2.f * qz2;
        const float r10 = 2.f * qxqy - 2.f * qzqw;
        const float r20 = 2.f * qxqz + 2.f * qyqw;
        const float r01 = 2.f * qxqy + 2.f * qzqw;
        const float r11 = 1.f - 2.f * qx2 - 2.f * qz2;
        const float r21 = 2.f * qyqz - 2.f * qxqw;
        const float r02 = 2.f * qxqz - 2.f * qyqw;
        const float r12 = 2.f * qyqz + 2.f * qxqw;
        const float r22 = 1.f - 2.f * qx2 - 2.f * qy2;

        const float cx = __ldg(pose + b * 3 + 0);
        const float cy = __ldg(pose + b * 3 + 1);
        const float cz = __ldg(pose + b * 3 + 2);
        const float t0 = cx * r00 + cy * r10 + cz * r20;
        const float t1 = cx * r01 + cy * r11 + cz * r21;
        const float t2 = cx * r02 + cy * r12 + cz * r22;

        if (tid == 0) {
            s_cam[0] = CAM_FL*r00; s_cam[1]  = CAM_FL*r10; s_cam[2]  = CAM_FL*r20; s_cam[3]  = CAM_FL*(-t0);
            s_cam[4] = CAM_FL*r01; s_cam[5]  = CAM_FL*r11; s_cam[6]  = CAM_FL*r21; s_cam[7]  = CAM_FL*(-t1);
            s_cam[8] = r02;        s_cam[9]  = r12;        s_cam[10] = r22;        s_cam[11] = -t2;
        }
    }
    __syncthreads();   // publishes s_cam and s_cnt

    const float a00 = s_cam[0], a01 = s_cam[1],  a02 = s_cam[2],  a03 = s_cam[3];
    const float a10 = s_cam[4], a11 = s_cam[5],  a12 = s_cam[6],  a13 = s_cam[7];
    const float a20 = s_cam[8], a21 = s_cam[9],  a22 = s_cam[10], a23 = s_cam[11];

    const float* dimg = depth + b * HW;
    float*       oimg = out   + b * HW;

    // ---------------- Phase 1: multiply-form cull + paired compaction ----------------
    const float C1 = 0.60653066f;   // exp(-0.5)
    const float C2 = 0.13533528f;   // exp(-2)

    float xs[2], ys[2], zv[2];
    bool  okv[2];
#pragma unroll
    for (int j = 0; j < 2; j++) {
        const float x = fmaf(X[j], a00, fmaf(Y[j], a01, fmaf(Z[j], a02, a03)));  // 540*x_cam
        const float y = fmaf(X[j], a10, fmaf(Y[j], a11, fmaf(Z[j], a12, a13)));  // 540*y_cam
        const float z = fmaf(X[j], a20, fmaf(Y[j], a21, fmaf(Z[j], a22, a23)));
        xs[j] = x; ys[j] = y; zv[j] = z;
        // cull without rcp: |540x| <= 322z && |540y| <= 242z && z > 0
        okv[j] = hv[j] && (z > 0.f) &&
                 (fabsf(x) <= 322.f * z) && (fabsf(y) <= 242.f * z);
    }

    const unsigned m0 = __ballot_sync(0xffffffffu, okv[0]);
    const unsigned m1 = __ballot_sync(0xffffffffu, okv[1]);
    const int n0  = __popc(m0);
    const int tot = n0 + __popc(m1);
    int idx[2] = {0, 0};
    if (tot) {
        const int lane = tid & 31;
        const unsigned lt = (1u << lane) - 1u;
        int base = 0;
        if (lane == 0) base = atomicAdd(&s_cnt, tot);
        base = __shfl_sync(0xffffffffu, base, 0);
        idx[0] = base + __popc(m0 & lt);
        idx[1] = base + n0 + __popc(m1 & lt);
    }

#pragma unroll
    for (int j = 0; j < 2; j++) {
        if (!okv[j]) continue;
        const float z    = zv[j];
        const float invz = __frcp_rn(z);
        const float px   = xs[j] * invz + HALF_W;
        const float py   = ys[j] * invz + HALF_H;
        const int   id   = idx[j];

        // exact re-verify (cull can disagree by ~1 ulp at the window edge)
        const bool exact = (fabsf(px - HALF_W) <= 322.f) && (fabsf(py - HALF_H) <= 242.f);

        if (id < CAP) {
            float* r = s_rec[id];
            // pre-zero ONLY the 8 weight slots; r[8..15] are dead unless written
            // (phase 2 predication on wx != 0 covers the !exact case).
            *(float4*)(r)     = make_float4(0.f, 0.f, 0.f, 0.f);
            *(float4*)(r + 4) = make_float4(0.f, 0.f, 0.f, 0.f);
            if (exact) {
                const float fx = floorf(px), fy = floorf(py);
                const int jb = (int)fx - 2;
                const int ib = (int)fy - 2;                 // in [-4, 480]
                const int bx = min(max(jb, 0) & ~3, 632);   // aligned 8-slot window
                const int off = jb - bx;                    // in [-2, 8]
                const float u = fx - px;
                const float v = fy - py;

                const float ax  = __expf(-0.5f * u * u);
                const float ex  = __expf(-u);
                const float exi = __frcp_rn(ex);
                int s;
                s = off + 0; if (s >= 0 && s <= 7) r[s] = ax * exi * exi * C2;
                s = off + 1; if (s >= 0 && s <= 7) r[s] = ax * exi * C1;
                s = off + 2; if (s >= 0 && s <= 7) r[s] = ax;
                s = off + 3; if (s >= 0 && s <= 7) r[s] = ax * ex * C1;
                s = off + 4; if (s >= 0 && s <= 7) r[s] = ax * ex * ex * C2;

                const float ay  = __expf(-0.5f * v * v);
                const float ey  = __expf(-v);
                const float eyi = __frcp_rn(ey);
                r[8]  = z;
                r[9]  = __int_as_float(bx | ((ib + 4) << 10));
                r[10] = ay * eyi * eyi * C2;
                r[11] = ay * eyi * C1;
                r[12] = ay;
                r[13] = ay * ey * C1;
                r[14] = ay * ey * ey * C2;
            }
        } else if (exact) {
            // overflow slow path (statistically unreachable): direct splat
            const float fx = floorf(px), fy = floorf(py);
            const int jb = (int)fx - 2, ib = (int)fy - 2;
            const float u = fx - px, v = fy - py;
            const float ax = __expf(-0.5f * u * u);
            const float ex = __expf(-u);
            const float exi = __frcp_rn(ex);
            const float wxv[5] = {ax*exi*exi*C2, ax*exi*C1, ax, ax*ex*C1, ax*ex*ex*C2};
            const float ay = __expf(-0.5f * v * v);
            const float ey = __expf(-v);
            const float eyi = __frcp_rn(ey);
            const float wyv[5] = {ay*eyi*eyi*C2, ay*eyi*C1, ay, ay*ey*C1, ay*ey*ey*C2};
            for (int ii = 0; ii < 5; ii++) {
                const int yy = ib + ii;
                if (yy < 0 || yy >= CAM_H) continue;
                for (int jj = 0; jj < 5; jj++) {
                    const int xx = jb + jj;
                    if (xx < 0 || xx >= CAM_W) continue;
                    const float d = __ldg(dimg + yy * CAM_W + xx);
                    if (z <= d) atomicAdd(oimg + yy * CAM_W + xx, wyv[ii] * wxv[jj]);
                }
            }
        }
    }

    __syncthreads();

    // ---------------- Phase 2: warp-coalesced splat ----------------
    // 8 consecutive lanes own the 8 aligned slots of one survivor; a warp
    // processes 4 survivors. Depth loads and reds hit 4 contiguous 32B
    // segments per warp-op (coalesced), 5 rows loaded up-front (MLP=5).
    const int cnt  = min(s_cnt, CAP);
    const int wid  = tid >> 5;
    const int lane = tid & 31;
    const int sub  = lane >> 3;     // 0..3: survivor within warp-task
    const int slot = lane & 7;      // 0..7: x-slot

    for (int s0 = wid * 4; s0 < cnt; s0 += (TPB / 32) * 4) {
        const int s = s0 + sub;
        if (s >= cnt) continue;

        const float* r = s_rec[s];
        const float wx = r[slot];
        const float z  = r[8];
        const int   pk = __float_as_int(r[9]);
        const int   bx = pk & 0x3ff;
        const int   ib = ((pk >> 10) & 0x1ff) - 4;

        const int base = ib * CAM_W + bx + slot;

        float dd[5];
        int   oo[5];
        bool  rk[5];
#pragma unroll
        for (int row = 0; row < 5; row++) {
            const int yy = ib + row;
            rk[row] = (yy >= 0) && (yy < CAM_H) && (wx != 0.f);
            oo[row] = base + row * CAM_W;
            dd[row] = rk[row] ? __ldg(dimg + oo[row]) : -1.f;
        }
#pragma unroll
        for (int row = 0; row < 5; row++) {
            if (rk[row] && z <= dd[row]) {
                atomicAdd(oimg + oo[row], r[10 + row] * wx);
            }
        }
    }
}

extern "C" void kernel_launch(void* const* d_in, const int* in_sizes, int n_in,
                              void* d_out, int out_size) {
    const float* locs  = (const float*)d_in[0];
    const float* pose  = (const float*)d_in[1];
    const float* rotq  = (const float*)d_in[2];
    const float* depth = (const float*)d_in[3];
    float* out = (float*)d_out;

    const int B = in_sizes[1] / 3;           // 4
    const int N = in_sizes[0] / (3 * B);     // 200000

    cudaMemsetAsync(d_out, 0, (size_t)out_size * sizeof(float), 0);

    dim3 grid((N + PB - 1) / PB, B);
    proj_kernel<<<grid, TPB>>>(locs, pose, rotq, depth, out, N);
}

// round 16
// speedup vs baseline: 1.4778x; 1.1404x over previous
#include <cuda_runtime.h>

#define CAM_FL  540.0f
#define HALF_W  320.0f
#define HALF_H  240.0f
#define CAM_W   640
#define CAM_H   480
#define HW      (CAM_H * CAM_W)
#define PB      512      // particles per block (2 per thread)
#define TPB     256      // threads per block
#define CAP     128      // smem survivor capacity (mean ~23/block; overflow -> slow path)

__global__ __launch_bounds__(TPB, 6) void proj_kernel(
    const float* __restrict__ locs,
    const float* __restrict__ pose,
    const float* __restrict__ rotq,
    const float* __restrict__ depth,
    float* __restrict__ out,
    int N)
{
    // s_cam rows: rows 0,1 pre-scaled by CAM_FL; p_cam[j] = X*a0 + Y*a1 + Z*a2 + a3
    __shared__ float s_cam[12];
    __shared__ float s_px[CAP];
    __shared__ float s_py[CAP];
    __shared__ float s_pz[CAP];
    __shared__ int   s_cnt;

    const int tid = threadIdx.x;
    const int b   = blockIdx.y;

    if (tid == 0) s_cnt = 0;

    const int  gpart = blockIdx.x * PB;
    const float* lpB = locs + ((long long)b * N + gpart) * 3;
    const int  i0 = 2 * tid;

    // ---- issue particle loads FIRST (overlap with warp-0 camera compute) ----
    float X[2], Y[2], Z[2];
    bool hv[2];
    if (gpart + PB <= N) {           // full block (uniform fast path)
        const float2 A  = *(const float2*)(lpB + i0 * 3);
        const float2 Bv = *(const float2*)(lpB + i0 * 3 + 2);
        const float2 Cv = *(const float2*)(lpB + i0 * 3 + 4);
        X[0] = A.x;  Y[0] = A.y;  Z[0] = Bv.x;
        X[1] = Bv.y; Y[1] = Cv.x; Z[1] = Cv.y;
        hv[0] = hv[1] = true;
    } else {
        hv[0] = (gpart + i0) < N;
        hv[1] = (gpart + i0 + 1) < N;
        X[0] = Y[0] = Z[0] = X[1] = Y[1] = Z[1] = 0.f;
        if (hv[0]) { X[0] = lpB[i0*3];   Y[0] = lpB[i0*3+1]; Z[0] = lpB[i0*3+2]; }
        if (hv[1]) { X[1] = lpB[i0*3+3]; Y[1] = lpB[i0*3+4]; Z[1] = lpB[i0*3+5]; }
    }

    // ---- warp 0: quaternion -> camera matrix (translation folded, rows 0/1 x CAM_FL) ----
    if (tid < 32) {
        float qx = __ldg(rotq + b * 4 + 0);
        float qy = __ldg(rotq + b * 4 + 1);
        float qz = __ldg(rotq + b * 4 + 2);
        float qw = __ldg(rotq + b * 4 + 3);
        float inv = rsqrtf(qx * qx + qy * qy + qz * qz + qw * qw);
        qx = -qx * inv; qy = -qy * inv; qz = -qz * inv; qw = qw * inv;

        const float qx2 = qx * qx, qy2 = qy * qy, qz2 = qz * qz;
        const float qxqy = qx * qy, qxqz = qx * qz, qxqw = qx * qw;
        const float qyqz = qy * qz, qyqw = qy * qw, qzqw = qz * qw;
        const float r00 = 1.f - 2.f * qy2 - 2.f * qz2;
        const float r10 = 2.f * qxqy - 2.f * qzqw;
        const float r20 = 2.f * qxqz + 2.f * qyqw;
        const float r01 = 2.f * qxqy + 2.f * qzqw;
        const float r11 = 1.f - 2.f * qx2 - 2.f * qz2;
        const float r21 = 2.f * qyqz - 2.f * qxqw;
        const float r02 = 2.f * qxqz - 2.f * qyqw;
        const float r12 = 2.f * qyqz + 2.f * qxqw;
        const float r22 = 1.f - 2.f * qx2 - 2.f * qy2;

        const float cx = __ldg(pose + b * 3 + 0);
        const float cy = __ldg(pose + b * 3 + 1);
        const float cz = __ldg(pose + b * 3 + 2);
        const float t0 = cx * r00 + cy * r10 + cz * r20;
        const float t1 = cx * r01 + cy * r11 + cz * r21;
        const float t2 = cx * r02 + cy * r12 + cz * r22;

        if (tid == 0) {
            s_cam[0] = CAM_FL*r00; s_cam[1]  = CAM_FL*r10; s_cam[2]  = CAM_FL*r20; s_cam[3]  = CAM_FL*(-t0);
            s_cam[4] = CAM_FL*r01; s_cam[5]  = CAM_FL*r11; s_cam[6]  = CAM_FL*r21; s_cam[7]  = CAM_FL*(-t1);
            s_cam[8] = r02;        s_cam[9]  = r12;        s_cam[10] = r22;        s_cam[11] = -t2;
        }
    }
    __syncthreads();   // publishes s_cam and s_cnt

    const float a00 = s_cam[0], a01 = s_cam[1],  a02 = s_cam[2],  a03 = s_cam[3];
    const float a10 = s_cam[4], a11 = s_cam[5],  a12 = s_cam[6],  a13 = s_cam[7];
    const float a20 = s_cam[8], a21 = s_cam[9],  a22 = s_cam[10], a23 = s_cam[11];

    const float* dimg = depth + b * HW;
    float*       oimg = out   + b * HW;

    // ---------------- Phase 1: multiply-form cull + paired compaction ----------------
    float xs[2], ys[2], zv[2];
    bool  okv[2];
#pragma unroll
    for (int j = 0; j < 2; j++) {
        const float x = fmaf(X[j], a00, fmaf(Y[j], a01, fmaf(Z[j], a02, a03)));  // 540*x_cam
        const float y = fmaf(X[j], a10, fmaf(Y[j], a11, fmaf(Z[j], a12, a13)));  // 540*y_cam
        const float z = fmaf(X[j], a20, fmaf(Y[j], a21, fmaf(Z[j], a22, a23)));
        xs[j] = x; ys[j] = y; zv[j] = z;
        // cull without rcp: |540x| <= 322z && |540y| <= 242z && z > 0
        okv[j] = hv[j] && (z > 0.f) &&
                 (fabsf(x) <= 322.f * z) && (fabsf(y) <= 242.f * z);
    }

    const unsigned m0 = __ballot_sync(0xffffffffu, okv[0]);
    const unsigned m1 = __ballot_sync(0xffffffffu, okv[1]);
    const int n0  = __popc(m0);
    const int tot = n0 + __popc(m1);
    int idx[2] = {0, 0};
    if (tot) {
        const int lane = tid & 31;
        const unsigned lt = (1u << lane) - 1u;
        int base = 0;
        if (lane == 0) base = atomicAdd(&s_cnt, tot);
        base = __shfl_sync(0xffffffffu, base, 0);
        idx[0] = base + __popc(m0 & lt);
        idx[1] = base + n0 + __popc(m1 & lt);
    }

#pragma unroll
    for (int j = 0; j < 2; j++) {
        if (!okv[j]) continue;
        const float z    = zv[j];
        const float invz = __frcp_rn(z);
        const float px   = xs[j] * invz + HALF_W;
        const float py   = ys[j] * invz + HALF_H;
        const int   id   = idx[j];

        // exact re-verify (cull can disagree by ~1 ulp at the window edge)
        const bool exact = (fabsf(px - HALF_W) <= 322.f) && (fabsf(py - HALF_H) <= 242.f);

        if (id < CAP) {
            // entire divergent section: 3 scalar stores
            s_px[id] = exact ? px : 1e9f;    // sentinel: all taps invalid
            s_py[id] = exact ? py : 1e9f;
            s_pz[id] = z;
        } else if (exact) {
            // overflow slow path (statistically unreachable): direct splat
            const float C1 = 0.60653066f, C2 = 0.13533528f;
            const float fx = floorf(px), fy = floorf(py);
            const int jb = (int)fx - 2, ib = (int)fy - 2;
            const float u = fx - px, v = fy - py;
            const float ax = __expf(-0.5f * u * u);
            const float ex = __expf(-u);
            const float exi = __frcp_rn(ex);
            const float wxv[5] = {ax*exi*exi*C2, ax*exi*C1, ax, ax*ex*C1, ax*ex*ex*C2};
            const float ay = __expf(-0.5f * v * v);
            const float ey = __expf(-v);
            const float eyi = __frcp_rn(ey);
            const float wyv[5] = {ay*eyi*eyi*C2, ay*eyi*C1, ay, ay*ey*C1, ay*ey*ey*C2};
            for (int ii = 0; ii < 5; ii++) {
                const int yy = ib + ii;
                if (yy < 0 || yy >= CAM_H) continue;
                for (int jj = 0; jj < 5; jj++) {
                    const int xx = jb + jj;
                    if (xx < 0 || xx >= CAM_W) continue;
                    const float d = __ldg(dimg + yy * CAM_W + xx);
                    if (z <= d) atomicAdd(oimg + yy * CAM_W + xx, wyv[ii] * wxv[jj]);
                }
            }
        }
    }

    __syncthreads();

    // ---------------- Phase 2: warp-coalesced splat, weights recomputed per lane ----------------
    // 8 consecutive lanes own the 8 aligned x-slots of one survivor; a warp
    // processes 4 survivors. Depth loads and reds hit 4 contiguous 32B
    // segments per warp-op (coalesced), 5 rows loaded up-front (MLP=5).
    // Each lane computes w = exp(-0.5*(dx^2+dy^2)) directly (reference formula).
    const int cnt  = min(s_cnt, CAP);
    const int wid  = tid >> 5;
    const int lane = tid & 31;
    const int sub  = lane >> 3;     // 0..3: survivor within warp-task
    const int slot = lane & 7;      // 0..7: x-slot

    for (int s0 = wid * 4; s0 < cnt; s0 += (TPB / 32) * 4) {
        const int s = s0 + sub;
        if (s >= cnt) continue;

        const float px = s_px[s];
        const float py = s_py[s];
        const float z  = s_pz[s];

        const float fx = floorf(px);
        const float fy = floorf(py);
        const int   jb = (int)fx - 2;
        const int   ib = (int)fy - 2;
        const int   bx = min(max(jb, 0) & ~3, 632);   // aligned 8-slot window

        const float jxf = (float)(bx + slot);
        const float dx  = jxf - px;
        const float dx2 = dx * dx;
        // tap exists iff jx in [floor(px)-2, floor(px)+2] (exact on int-valued floats)
        const bool validx = fabsf(jxf - fx) <= 2.0f;

        const int base = ib * CAM_W + bx + slot;

        float dd[5];
        int   oo[5];
        bool  rk[5];
#pragma unroll
        for (int row = 0; row < 5; row++) {
            const int yy = ib + row;
            rk[row] = (yy >= 0) && (yy < CAM_H) && validx;
            oo[row] = base + row * CAM_W;
            dd[row] = rk[row] ? __ldg(dimg + oo[row]) : -1.f;
        }
#pragma unroll
        for (int row = 0; row < 5; row++) {
            if (rk[row] && z <= dd[row]) {
                const float dy = (float)(ib + row) - py;
                const float w  = __expf(-0.5f * fmaf(dy, dy, dx2));
                atomicAdd(oimg + oo[row], w);
            }
        }
    }
}

extern "C" void kernel_launch(void* const* d_in, const int* in_sizes, int n_in,
                              void* d_out, int out_size) {
    const float* locs  = (const float*)d_in[0];
    const float* pose  = (const float*)d_in[1];
    const float* rotq  = (const float*)d_in[2];
    const float* depth = (const float*)d_in[3];
    float* out = (float*)d_out;

    const int B = in_sizes[1] / 3;           // 4
    const int N = in_sizes[0] / (3 * B);     // 200000

    cudaMemsetAsync(d_out, 0, (size_t)out_size * sizeof(float), 0);

    dim3 grid((N + PB - 1) / PB, B);
    proj_kernel<<<grid, TPB>>>(locs, pose, rotq, depth, out, N);
}

// round 17
// speedup vs baseline: 1.5000x; 1.0150x over previous
#include <cuda_runtime.h>

#define CAM_FL  540.0f
#define HALF_W  320.0f
#define HALF_H  240.0f
#define CAM_W   640
#define CAM_H   480
#define HW      (CAM_H * CAM_W)
#define PB      1024     // particles per block (4 per thread)
#define TPB     256      // threads per block
#define CAP     128      // smem survivor capacity (mean ~46/block; overflow -> slow path)

__global__ __launch_bounds__(TPB, 6) void proj_kernel(
    const float* __restrict__ locs,
    const float* __restrict__ pose,
    const float* __restrict__ rotq,
    const float* __restrict__ depth,
    float* __restrict__ out,
    int N)
{
    // s_cam rows: rows 0,1 pre-scaled by CAM_FL; p_cam[j] = X*a0 + Y*a1 + Z*a2 + a3
    __shared__ float4 s_cam[3];
    __shared__ float s_px[CAP];
    __shared__ float s_py[CAP];
    __shared__ float s_pz[CAP];
    __shared__ int   s_cnt;

    const int tid = threadIdx.x;
    const int b   = blockIdx.y;

    if (tid == 0) s_cnt = 0;

    const int  gpart = blockIdx.x * PB;
    const float* lpB = locs + ((long long)b * N + gpart) * 3;
    const int  i0 = 4 * tid;

    // ---- issue particle loads FIRST (overlap with warp-0 camera compute) ----
    float X[4], Y[4], Z[4];
    bool hv[4];
    if (gpart + PB <= N) {           // full block: 3x aligned LDG.128 (48B/thread)
        const float4* p = (const float4*)(lpB + i0 * 3);
        const float4 A  = p[0];
        const float4 Bv = p[1];
        const float4 Cv = p[2];
        X[0] = A.x;  Y[0] = A.y;  Z[0] = A.z;
        X[1] = A.w;  Y[1] = Bv.x; Z[1] = Bv.y;
        X[2] = Bv.z; Y[2] = Bv.w; Z[2] = Cv.x;
        X[3] = Cv.y; Y[3] = Cv.z; Z[3] = Cv.w;
        hv[0] = hv[1] = hv[2] = hv[3] = true;
    } else {
#pragma unroll
        for (int j = 0; j < 4; j++) {
            hv[j] = (gpart + i0 + j) < N;
            X[j] = Y[j] = Z[j] = 0.f;
            if (hv[j]) {
                X[j] = lpB[(i0 + j) * 3];
                Y[j] = lpB[(i0 + j) * 3 + 1];
                Z[j] = lpB[(i0 + j) * 3 + 2];
            }
        }
    }

    // ---- warp 0: quaternion -> camera matrix (translation folded, rows 0/1 x CAM_FL) ----
    if (tid < 32) {
        float qx = __ldg(rotq + b * 4 + 0);
        float qy = __ldg(rotq + b * 4 + 1);
        float qz = __ldg(rotq + b * 4 + 2);
        float qw = __ldg(rotq + b * 4 + 3);
        float inv = rsqrtf(qx * qx + qy * qy + qz * qz + qw * qw);
        qx = -qx * inv; qy = -qy * inv; qz = -qz * inv; qw = qw * inv;

        const float qx2 = qx * qx, qy2 = qy * qy, qz2 = qz * qz;
        const float qxqy = qx * qy, qxqz = qx * qz, qxqw = qx * qw;
        const float qyqz = qy * qz, qyqw = qy * qw, qzqw = qz * qw;
        const float r00 = 1.f - 2.f * qy2 - 2.f * qz2;
        const float r10 = 2.f * qxqy - 2.f * qzqw;
        const float r20 = 2.f * qxqz + 2.f * qyqw;
        const float r01 = 2.f * qxqy + 2.f * qzqw;
        const float r11 = 1.f - 2.f * qx2 - 2.f * qz2;
        const float r21 = 2.f * qyqz - 2.f * qxqw;
        const float r02 = 2.f * qxqz - 2.f * qyqw;
        const float r12 = 2.f * qyqz + 2.f * qxqw;
        const float r22 = 1.f - 2.f * qx2 - 2.f * qy2;

        const float cx = __ldg(pose + b * 3 + 0);
        const float cy = __ldg(pose + b * 3 + 1);
        const float cz = __ldg(pose + b * 3 + 2);
        const float t0 = cx * r00 + cy * r10 + cz * r20;
        const float t1 = cx * r01 + cy * r11 + cz * r21;
        const float t2 = cx * r02 + cy * r12 + cz * r22;

        if (tid == 0) {
            s_cam[0] = make_float4(CAM_FL*r00, CAM_FL*r10, CAM_FL*r20, CAM_FL*(-t0));
            s_cam[1] = make_float4(CAM_FL*r01, CAM_FL*r11, CAM_FL*r21, CAM_FL*(-t1));
            s_cam[2] = make_float4(r02, r12, r22, -t2);
        }
    }
    __syncthreads();   // publishes s_cam and s_cnt

    const float4 c0 = s_cam[0];
    const float4 c1 = s_cam[1];
    const float4 c2 = s_cam[2];

    const float* dimg = depth + b * HW;
    float*       oimg = out   + b * HW;

    // ---------------- Phase 1: multiply-form cull, 2 rounds of 2 particles ----------------
#pragma unroll
    for (int pair = 0; pair < 2; pair++) {
        float xs[2], ys[2], zv[2];
        bool  okv[2];
#pragma unroll
        for (int u = 0; u < 2; u++) {
            const int j = pair * 2 + u;
            const float x = fmaf(X[j], c0.x, fmaf(Y[j], c0.y, fmaf(Z[j], c0.z, c0.w)));  // 540*x_cam
            const float y = fmaf(X[j], c1.x, fmaf(Y[j], c1.y, fmaf(Z[j], c1.z, c1.w)));  // 540*y_cam
            const float z = fmaf(X[j], c2.x, fmaf(Y[j], c2.y, fmaf(Z[j], c2.z, c2.w)));
            xs[u] = x; ys[u] = y; zv[u] = z;
            // cull without rcp: |540x| <= 322z && |540y| <= 242z && z > 0
            okv[u] = hv[j] && (z > 0.f) &&
                     (fabsf(x) <= 322.f * z) && (fabsf(y) <= 242.f * z);
        }

        const unsigned m0 = __ballot_sync(0xffffffffu, okv[0]);
        const unsigned m1 = __ballot_sync(0xffffffffu, okv[1]);
        const int n0  = __popc(m0);
        const int tot = n0 + __popc(m1);
        int idx[2] = {0, 0};
        if (tot) {
            const int lane = tid & 31;
            const unsigned lt = (1u << lane) - 1u;
            int base = 0;
            if (lane == 0) base = atomicAdd(&s_cnt, tot);
            base = __shfl_sync(0xffffffffu, base, 0);
            idx[0] = base + __popc(m0 & lt);
            idx[1] = base + n0 + __popc(m1 & lt);
        }

#pragma unroll
        for (int u = 0; u < 2; u++) {
            if (!okv[u]) continue;
            const float z    = zv[u];
            const float invz = __frcp_rn(z);
            const float px   = xs[u] * invz + HALF_W;
            const float py   = ys[u] * invz + HALF_H;
            const int   id   = idx[u];

            // exact re-verify (cull can disagree by ~1 ulp at the window edge)
            const bool exact = (fabsf(px - HALF_W) <= 322.f) && (fabsf(py - HALF_H) <= 242.f);

            if (id < CAP) {
                // entire divergent section: 3 scalar stores
                s_px[id] = exact ? px : 1e9f;    // sentinel: all taps invalid
                s_py[id] = exact ? py : 1e9f;
                s_pz[id] = z;
            } else if (exact) {
                // overflow slow path (statistically unreachable): direct splat
                const float C1 = 0.60653066f, C2 = 0.13533528f;
                const float fx = floorf(px), fy = floorf(py);
                const int jb = (int)fx - 2, ib = (int)fy - 2;
                const float uu = fx - px, vv = fy - py;
                const float ax = __expf(-0.5f * uu * uu);
                const float ex = __expf(-uu);
                const float exi = __frcp_rn(ex);
                const float wxv[5] = {ax*exi*exi*C2, ax*exi*C1, ax, ax*ex*C1, ax*ex*ex*C2};
                const float ay = __expf(-0.5f * vv * vv);
                const float ey = __expf(-vv);
                const float eyi = __frcp_rn(ey);
                const float wyv[5] = {ay*eyi*eyi*C2, ay*eyi*C1, ay, ay*ey*C1, ay*ey*ey*C2};
                for (int ii = 0; ii < 5; ii++) {
                    const int yy = ib + ii;
                    if (yy < 0 || yy >= CAM_H) continue;
                    for (int jj = 0; jj < 5; jj++) {
                        const int xx = jb + jj;
                        if (xx < 0 || xx >= CAM_W) continue;
                        const float d = __ldg(dimg + yy * CAM_W + xx);
                        if (z <= d) atomicAdd(oimg + yy * CAM_W + xx, wyv[ii] * wxv[jj]);
                    }
                }
            }
        }
    }

    __syncthreads();

    // ---------------- Phase 2: warp-coalesced splat, weights recomputed per lane ----------------
    // 8 consecutive lanes own the 8 aligned x-slots of one survivor; a warp
    // processes 4 survivors. Depth loads and reds hit 4 contiguous 32B
    // segments per warp-op (coalesced), 5 rows loaded up-front (MLP=5).
    // Each lane computes w = exp(-0.5*(dx^2+dy^2)) directly (reference formula).
    const int cnt  = min(s_cnt, CAP);
    const int wid  = tid >> 5;
    const int lane = tid & 31;
    const int sub  = lane >> 3;     // 0..3: survivor within warp-task
    const int slot = lane & 7;      // 0..7: x-slot

    for (int s0 = wid * 4; s0 < cnt; s0 += (TPB / 32) * 4) {
        const int s = s0 + sub;
        if (s >= cnt) continue;

        const float px = s_px[s];
        const float py = s_py[s];
        const float z  = s_pz[s];

        const float fx = floorf(px);
        const float fy = floorf(py);
        const int   jb = (int)fx - 2;
        const int   ib = (int)fy - 2;
        const int   bx = min(max(jb, 0) & ~3, 632);   // aligned 8-slot window

        const float jxf = (float)(bx + slot);
        const float dx  = jxf - px;
        const float dx2 = dx * dx;
        // tap exists iff jx in [floor(px)-2, floor(px)+2] (exact on int-valued floats)
        const bool validx = fabsf(jxf - fx) <= 2.0f;

        const int base = ib * CAM_W + bx + slot;

        float dd[5];
        int   oo[5];
        bool  rk[5];
#pragma unroll
        for (int row = 0; row < 5; row++) {
            const int yy = ib + row;
            rk[row] = (yy >= 0) && (yy < CAM_H) && validx;
            oo[row] = base + row * CAM_W;
            dd[row] = rk[row] ? __ldg(dimg + oo[row]) : -1.f;
        }
#pragma unroll
        for (int row = 0; row < 5; row++) {
            if (rk[row] && z <= dd[row]) {
                const float dy = (float)(ib + row) - py;
                const float w  = __expf(-0.5f * fmaf(dy, dy, dx2));
                atomicAdd(oimg + oo[row], w);
            }
        }
    }
}

extern "C" void kernel_launch(void* const* d_in, const int* in_sizes, int n_in,
                              void* d_out, int out_size) {
    const float* locs  = (const float*)d_in[0];
    const float* pose  = (const float*)d_in[1];
    const float* rotq  = (const float*)d_in[2];
    const float* depth = (const float*)d_in[3];
    float* out = (float*)d_out;

    const int B = in_sizes[1] / 3;           // 4
    const int N = in_sizes[0] / (3 * B);     // 200000

    cudaMemsetAsync(d_out, 0, (size_t)out_size * sizeof(float), 0);

    dim3 grid((N + PB - 1) / PB, B);
    proj_kernel<<<grid, TPB>>>(locs, pose, rotq, depth, out, N);
}